// round 1
// baseline (speedup 1.0000x reference)
#include <cuda_runtime.h>

// Problem constants
#define B_    2
#define S_    2048
#define DM    1024
#define H_    16
#define HD    64
#define MROWS (B_ * S_)          // 4096

typedef unsigned long long u64;
typedef unsigned char u8;

// ---------------- scratch (device globals; no allocation allowed) ----------------
__device__ __align__(16) u8   g_bin[3][MROWS * DM];      // thresholded Q/K/V as bytes (12.6 MB)
__device__ __align__(16) u64  g_qbits[B_ * H_ * S_];     // packed Q bits per (b,h,s)
__device__ __align__(16) u64  g_kbits[B_ * H_ * S_];     // packed K bits
__device__ __align__(16) float g_vhead[B_ * H_ * S_ * HD]; // V head-major fp32 (16 MB)
__device__ __align__(16) float g_attn[MROWS * DM];       // attention output (16 MB)

// ---------------- packed f32x2 helpers ----------------
union F2U { float2 f; u64 u; };

__device__ __forceinline__ u64 pack2(float x, float y) {
    F2U t; t.f.x = x; t.f.y = y; return t.u;
}
__device__ __forceinline__ void ffma2(u64& d, u64 a, u64 b) {
    asm("fma.rn.f32x2 %0, %1, %2, %0;" : "+l"(d) : "l"(a), "l"(b));
}

// ---------------- binary-weight GEMM: C = threshold(A @ W^T + bias) ----------------
// A: [MROWS, DM] fp32 row-major (MODE==1 uses g_attn as A)
// W: [DM, DM] fp32 row-major ({0,1} values)
// MODE 0: write u8 {0,1} to g_bin[out_sel]
// MODE 1: write fp32 {0.f,1.f} to out_f32 (final output)
template <int MODE>
__global__ void __launch_bounds__(256) gemm_bin(const float* __restrict__ A_ext,
                                               const float* __restrict__ W,
                                               const float* __restrict__ bias,
                                               float* __restrict__ out_f32,
                                               int out_sel) {
    const int BM = 128, BN = 128, BK = 16;
    __shared__ float As[BK][BM];
    __shared__ float Bs[BK][BN];

    const float* A = (MODE == 1) ? g_attn : A_ext;

    const int m0 = blockIdx.y * BM;
    const int n0 = blockIdx.x * BN;
    const int tid = threadIdx.x;
    const int tn = tid & 15;        // 0..15 -> 8 cols each
    const int tm = tid >> 4;        // 0..15 -> 8 rows each

    u64 acc[8][4];
#pragma unroll
    for (int i = 0; i < 8; i++)
#pragma unroll
        for (int p = 0; p < 4; p++) acc[i][p] = 0ull;

    for (int k0 = 0; k0 < DM; k0 += BK) {
        // cooperative loads: 512 float4 per operand tile, 2 per thread
#pragma unroll
        for (int t = 0; t < 2; t++) {
            int slot = tid * 2 + t;          // 0..511
            int row = slot >> 2;             // 0..127
            int c4 = slot & 3;               // which float4 in the 16-wide k slab
            float4 va = *(const float4*)(A + (size_t)(m0 + row) * DM + k0 + c4 * 4);
            As[c4 * 4 + 0][row] = va.x; As[c4 * 4 + 1][row] = va.y;
            As[c4 * 4 + 2][row] = va.z; As[c4 * 4 + 3][row] = va.w;
            float4 vb = *(const float4*)(W + (size_t)(n0 + row) * DM + k0 + c4 * 4);
            Bs[c4 * 4 + 0][row] = vb.x; Bs[c4 * 4 + 1][row] = vb.y;
            Bs[c4 * 4 + 2][row] = vb.z; Bs[c4 * 4 + 3][row] = vb.w;
        }
        __syncthreads();

#pragma unroll
        for (int kk = 0; kk < BK; kk++) {
            float4 a0 = *(const float4*)&As[kk][tm * 8];
            float4 a1 = *(const float4*)&As[kk][tm * 8 + 4];
            float4 b0 = *(const float4*)&Bs[kk][tn * 8];
            float4 b1 = *(const float4*)&Bs[kk][tn * 8 + 4];
            u64 bp[4] = { pack2(b0.x, b0.y), pack2(b0.z, b0.w),
                          pack2(b1.x, b1.y), pack2(b1.z, b1.w) };
            float av[8] = { a0.x, a0.y, a0.z, a0.w, a1.x, a1.y, a1.z, a1.w };
#pragma unroll
            for (int i = 0; i < 8; i++) {
                u64 ap = pack2(av[i], av[i]);
#pragma unroll
                for (int p = 0; p < 4; p++) ffma2(acc[i][p], ap, bp[p]);
            }
        }
        __syncthreads();
    }

    // epilogue: bias + threshold
#pragma unroll
    for (int i = 0; i < 8; i++) {
        int row = m0 + tm * 8 + i;
#pragma unroll
        for (int p = 0; p < 4; p++) {
            int col = n0 + tn * 8 + 2 * p;
            F2U t; t.u = acc[i][p];
            float c0 = t.f.x + bias[col];
            float c1 = t.f.y + bias[col + 1];
            if (MODE == 0) {
                u8* o = g_bin[out_sel];
                o[(size_t)row * DM + col]     = (c0 > 0.5f) ? 1 : 0;
                o[(size_t)row * DM + col + 1] = (c1 > 0.5f) ? 1 : 0;
            } else {
                out_f32[(size_t)row * DM + col]     = (c0 > 0.5f) ? 1.0f : 0.0f;
                out_f32[(size_t)row * DM + col + 1] = (c1 > 0.5f) ? 1.0f : 0.0f;
            }
        }
    }
}

// ---------------- pack Q/K bytes into 64-bit head masks ----------------
__global__ void pack_qk_kernel() {
    int idx = blockIdx.x * blockDim.x + threadIdx.x;   // 0 .. 2*B*H*S-1
    int which = idx >> 16;            // B*H*S = 65536
    int r = idx & 0xFFFF;
    int b = r >> 15;                  // H*S = 32768
    int h = (r >> 11) & 15;           // S = 2048
    int s = r & 2047;

    const u8* src = g_bin[which] + ((size_t)(b * S_ + s) * DM + h * HD);
    const u64* s8 = (const u64*)src;  // 64-byte aligned chunk
    u64 bits = 0;
#pragma unroll
    for (int w = 0; w < 8; w++) {
        u64 c = s8[w];
#pragma unroll
        for (int j = 0; j < 8; j++)
            bits |= ((c >> (8 * j)) & 1ull) << (w * 8 + j);
    }
    u64* dst = which ? g_kbits : g_qbits;
    dst[((size_t)(b * H_ + h)) * S_ + s] = bits;
}

// ---------------- V reorder to head-major fp32 ----------------
__global__ void v_reorder_kernel() {
    int idx = blockIdx.x * blockDim.x + threadIdx.x;   // 0 .. B*H*S*HD-1
    int d = idx & 63;
    int t = idx >> 6;
    int s = t & 2047;
    int t2 = t >> 11;
    int h = t2 & 15;
    int b = t2 >> 4;
    g_vhead[idx] = (float)g_bin[2][(size_t)(b * S_ + s) * DM + h * HD + d];
}

// ---------------- attention: popcount scores + squared-softmax + PV ----------------
// score count c in [0,64]; s = c/8; w1 = e^{s} = exp2f(c * 0.125*log2(e)); w2 = w1*w1 = e^{2s}
// out_d = sum_k w2_k v_kd / (Z2 + 1e-8 * Z1^2)   (shift-invariant, incl. the eps)
__global__ void __launch_bounds__(128) attn_kernel() {
    const int KT = 64;
    __shared__ u64 kb[KT];
    __shared__ __align__(16) float vs[KT * HD];   // 16 KB

    const int q0 = blockIdx.x * 128;
    const int h = blockIdx.y;
    const int b = blockIdx.z;
    const int bh = b * H_ + h;
    const int tid = threadIdx.x;

    const u64 q = g_qbits[(size_t)bh * S_ + q0 + tid];

    u64 acc[32];
#pragma unroll
    for (int j = 0; j < 32; j++) acc[j] = 0ull;
    float Z1 = 0.0f, Z2 = 0.0f;

    const float C1 = 0.18033688011112042f;   // 0.125 * log2(e)

    for (int kt = 0; kt < S_; kt += KT) {
        if (tid < KT) kb[tid] = g_kbits[(size_t)bh * S_ + kt + tid];
        const float4* vsrc = (const float4*)(g_vhead + ((size_t)bh * S_ + kt) * HD);
        float4* vdst = (float4*)vs;
#pragma unroll
        for (int t = 0; t < 8; t++)             // KT*HD/4 = 1024 float4, 128 threads
            vdst[t * 128 + tid] = vsrc[t * 128 + tid];
        __syncthreads();

#pragma unroll 2
        for (int kk = 0; kk < KT; kk++) {
            int cnt = __popcll(q & kb[kk]);
            float w1 = exp2f((float)cnt * C1);
            float w2 = w1 * w1;
            Z1 += w1;
            Z2 += w2;
            u64 wp = pack2(w2, w2);
            const float4* vr4 = (const float4*)(vs + kk * HD);
#pragma unroll
            for (int j = 0; j < 16; j++) {
                float4 v4 = vr4[j];
                ffma2(acc[2 * j],     wp, pack2(v4.x, v4.y));
                ffma2(acc[2 * j + 1], wp, pack2(v4.z, v4.w));
            }
        }
        __syncthreads();
    }

    float inv = 1.0f / (Z2 + 1e-8f * Z1 * Z1);
    int m = b * S_ + q0 + tid;
    float* dst = g_attn + (size_t)m * DM + h * HD;
#pragma unroll
    for (int j = 0; j < 32; j++) {
        F2U t; t.u = acc[j];
        dst[2 * j]     = t.f.x * inv;
        dst[2 * j + 1] = t.f.y * inv;
    }
}

// ---------------- launch ----------------
extern "C" void kernel_launch(void* const* d_in, const int* in_sizes, int n_in,
                              void* d_out, int out_size) {
    const float* x  = (const float*)d_in[0];
    const float* wq = (const float*)d_in[1];
    const float* bq = (const float*)d_in[2];
    const float* wk = (const float*)d_in[3];
    const float* bk = (const float*)d_in[4];
    const float* wv = (const float*)d_in[5];
    const float* bv = (const float*)d_in[6];
    const float* wo = (const float*)d_in[7];
    const float* bo = (const float*)d_in[8];
    float* out = (float*)d_out;

    dim3 ggrid(DM / 128, MROWS / 128);   // (8, 32)

    // Q/K/V binary projections
    gemm_bin<0><<<ggrid, 256>>>(x, wq, bq, nullptr, 0);
    gemm_bin<0><<<ggrid, 256>>>(x, wk, bk, nullptr, 1);
    gemm_bin<0><<<ggrid, 256>>>(x, wv, bv, nullptr, 2);

    // pack bits + reorder V
    pack_qk_kernel<<<(2 * B_ * H_ * S_) / 256, 256>>>();
    v_reorder_kernel<<<(B_ * H_ * S_ * HD) / 256, 256>>>();

    // attention
    dim3 agrid(S_ / 128, H_, B_);        // (16, 16, 2)
    attn_kernel<<<agrid, 128>>>();

    // final binary projection -> d_out (fp32)
    gemm_bin<1><<<ggrid, 256>>>(nullptr, wo, bo, out, 0);
}

// round 5
// speedup vs baseline: 2.1908x; 2.1908x over previous
#include <cuda_runtime.h>
#include <cuda_bf16.h>
#include <cstdint>

#define B_    2
#define S_    2048
#define DM    1024
#define H_    16
#define HD    64
#define MROWS 4096
#define XN    (MROWS * DM)      // 4194304
#define WN    (DM * DM)         // 1048576

typedef unsigned long long u64;
typedef unsigned int u32;

// ---------------- scratch (device globals; no allocation allowed) ----------------
__device__ __align__(16) __nv_bfloat16 g_xb[XN];          // x in bf16 (8 MB)
__device__ __align__(16) __nv_bfloat16 g_wb[3 * WN];      // wq|wk|wv stacked bf16 (6 MB)
__device__ __align__(16) __nv_bfloat16 g_wob[WN];         // wo bf16 (2 MB)
__device__ __align__(16) u64  g_qbits[B_ * H_ * S_];      // packed Q bits
__device__ __align__(16) u64  g_kbits[B_ * H_ * S_];      // packed K bits
__device__ __align__(16) float g_vhead[B_ * H_ * S_ * HD];// V head-major fp32 (16 MB)
__device__ __align__(16) __nv_bfloat16 g_attnb[XN];       // attention out bf16 (8 MB)

// ---------------- helpers ----------------
union F2U { float2 f; u64 u; };
__device__ __forceinline__ u64 pack2(float x, float y) { F2U t; t.f.x = x; t.f.y = y; return t.u; }
__device__ __forceinline__ void ffma2(u64& d, u64 a, u64 b) {
    asm("fma.rn.f32x2 %0, %1, %2, %0;" : "+l"(d) : "l"(a), "l"(b));
}
__device__ __forceinline__ u32 smem_u32(const void* p) {
    u32 a;
    asm("{ .reg .u64 t; cvta.to.shared.u64 t, %1; cvt.u32.u64 %0, t; }" : "=r"(a) : "l"(p));
    return a;
}
__device__ __forceinline__ void ldsm_x4(u32* r, u32 addr) {
    asm volatile("ldmatrix.sync.aligned.m8n8.x4.shared.b16 {%0,%1,%2,%3}, [%4];"
        : "=r"(r[0]), "=r"(r[1]), "=r"(r[2]), "=r"(r[3]) : "r"(addr));
}
__device__ __forceinline__ void mma16816(float* c, const u32* a, const u32* b) {
    asm volatile("mma.sync.aligned.m16n8k16.row.col.f32.bf16.bf16.f32 "
        "{%0,%1,%2,%3}, {%4,%5,%6,%7}, {%8,%9}, {%0,%1,%2,%3};"
        : "+f"(c[0]), "+f"(c[1]), "+f"(c[2]), "+f"(c[3])
        : "r"(a[0]), "r"(a[1]), "r"(a[2]), "r"(a[3]), "r"(b[0]), "r"(b[1]));
}
#define SW128(o) ((o) ^ ((((u32)(o)) >> 3) & 0x70))

// ---------------- fp32 -> bf16 conversion of x and all weights ----------------
__global__ void __launch_bounds__(256) convert_kernel(const float* __restrict__ x,
                                                      const float* __restrict__ wq,
                                                      const float* __restrict__ wk,
                                                      const float* __restrict__ wv,
                                                      const float* __restrict__ wo) {
    size_t i = ((size_t)blockIdx.x * blockDim.x + threadIdx.x) * 4;
    const float* src;
    __nv_bfloat16* dst;
    size_t off;
    if (i < XN) { src = x; dst = g_xb; off = i; }
    else {
        size_t j = i - XN;
        int w = (int)(j >> 20);
        off = j & (WN - 1);
        src = (w == 0) ? wq : (w == 1) ? wk : (w == 2) ? wv : wo;
        dst = (w < 3) ? (g_wb + (size_t)w * WN) : g_wob;
    }
    float4 v = *(const float4*)(src + off);
    __nv_bfloat162 lo = __floats2bfloat162_rn(v.x, v.y);
    __nv_bfloat162 hi = __floats2bfloat162_rn(v.z, v.w);
    uint2 pk;
    pk.x = *(u32*)&lo; pk.y = *(u32*)&hi;
    *(uint2*)(dst + off) = pk;
}

// ---------------- HMMA GEMM: C = threshold(A @ W^T + bias) ----------------
// MODE 0: A=g_xb, W=g_wb (3072 N-rows: q|k|v), epilogue -> g_qbits/g_kbits masks, g_vhead floats
// MODE 1: A=g_attnb, W=g_wob, epilogue -> out fp32 {0,1}
// CTA tile M=128 N=128, 8 warps as 4(m) x 2(n): warp tile 32x64. K chunks of 64.
template <int MODE>
__global__ void __launch_bounds__(256) gemm_mma(const float* __restrict__ bb0,
                                               const float* __restrict__ bb1,
                                               const float* __restrict__ bb2,
                                               float* __restrict__ out) {
    __shared__ __align__(16) __nv_bfloat16 As[128 * 64];
    __shared__ __align__(16) __nv_bfloat16 Bs[128 * 64];
    __shared__ float sbias[128];

    const int tid = threadIdx.x, lane = tid & 31, wid = tid >> 5;
    const int warp_m = wid & 3, warp_n = wid >> 2;
    const int m0 = blockIdx.y * 128, n0g = blockIdx.x * 128;
    const int p = (MODE == 0) ? (n0g >> 10) : 0;
    const int hd_off = (MODE == 0) ? (n0g & 1023) : n0g;
    const float* bp = (MODE == 0) ? (p == 0 ? bb0 : (p == 1 ? bb1 : bb2)) : bb0;
    const __nv_bfloat16* A = (MODE == 0) ? g_xb : g_attnb;
    const __nv_bfloat16* W = (MODE == 0) ? g_wb : g_wob;

    if (tid < 128) sbias[tid] = bp[hd_off + tid];

    float acc[2][8][4];
#pragma unroll
    for (int fm = 0; fm < 2; fm++)
#pragma unroll
        for (int fn = 0; fn < 8; fn++)
#pragma unroll
            for (int e = 0; e < 4; e++) acc[fm][fn][e] = 0.0f;

    const u32 sA = smem_u32(As), sB = smem_u32(Bs);
    // ldmatrix per-thread address bases (row*128 bytes, swizzle = (row&7)<<4 on byte bits 4-6)
    const int a_row = warp_m * 32 + (lane & 15);
    const u32 a_base0 = sA + (u32)a_row * 128;
    const u32 a_base1 = a_base0 + 16 * 128;
    const u32 a_kx = (u32)((lane >> 4) << 4);          // k-half select: 0 or 16 bytes
    const u32 a_sw = (u32)(a_row & 7) << 4;
    // B groups: gi = lane>>3: {n+i,+0},{n+i,+16},{n+8+i,+0},{n+8+i,+16}
    const int b_rin = lane & 7;
    const int b_nadd = ((lane >> 4) & 1) * 8;
    const u32 b_kx = (u32)(((lane >> 3) & 1) << 4);
    const u32 b_sw = (u32)b_rin << 4;
    u32 b_base[4];
#pragma unroll
    for (int g = 0; g < 4; g++)
        b_base[g] = sB + (u32)(warp_n * 64 + g * 16 + b_nadd + b_rin) * 128;

    for (int c = 0; c < 16; c++) {
        const int k0 = c * 64;
#pragma unroll
        for (int i = 0; i < 4; i++) {
            int e = tid + i * 256;            // 0..1023: 128 rows x 8 segs of 16B
            int row = e >> 3, seg = e & 7;
            u32 so = SW128((u32)(row * 128 + seg * 16));
            *(uint4*)((char*)As + so) = *(const uint4*)(A + (size_t)(m0 + row) * DM + k0 + seg * 8);
            *(uint4*)((char*)Bs + so) = *(const uint4*)(W + (size_t)(n0g + row) * DM + k0 + seg * 8);
        }
        __syncthreads();
#pragma unroll
        for (int kc = 0; kc < 4; kc++) {
            const u32 kb = (u32)(kc * 32);
            u32 af[2][4];
            ldsm_x4(af[0], a_base0 + ((kb + a_kx) ^ a_sw));
            ldsm_x4(af[1], a_base1 + ((kb + a_kx) ^ a_sw));
            u32 bf[4][4];
#pragma unroll
            for (int g = 0; g < 4; g++)
                ldsm_x4(bf[g], b_base[g] + ((kb + b_kx) ^ b_sw));
#pragma unroll
            for (int fm = 0; fm < 2; fm++)
#pragma unroll
                for (int fn = 0; fn < 8; fn++)
                    mma16816(acc[fm][fn], af[fm], &bf[fn >> 1][(fn & 1) * 2]);
        }
        __syncthreads();
    }

    // ---------------- epilogue: bias + threshold, fused output formats ----------------
    // C frag mapping: c[half*2+e] -> row = gr + half*8, col = gc*2 + e
    const int gr = lane >> 2, gc = lane & 3;
    const int head_base = hd_off >> 6;

#pragma unroll
    for (int fm = 0; fm < 2; fm++) {
#pragma unroll
        for (int half = 0; half < 2; half++) {
            const int row = m0 + warp_m * 32 + fm * 16 + half * 8 + gr;
            const int b = row >> 11, s = row & 2047;

            if (MODE == 0 && p < 2) {
                u64 mask = 0;
#pragma unroll
                for (int fn = 0; fn < 8; fn++) {
                    float c0 = acc[fm][fn][half * 2 + 0] + sbias[warp_n * 64 + fn * 8 + gc * 2];
                    float c1 = acc[fm][fn][half * 2 + 1] + sbias[warp_n * 64 + fn * 8 + gc * 2 + 1];
                    mask |= (u64)(c0 > 0.5f) << (fn * 8 + gc * 2);
                    mask |= (u64)(c1 > 0.5f) << (fn * 8 + gc * 2 + 1);
                }
                mask |= __shfl_xor_sync(0xFFFFFFFFu, mask, 1);
                mask |= __shfl_xor_sync(0xFFFFFFFFu, mask, 2);
                if (gc == 0) {
                    const int h = head_base + warp_n;
                    ((p == 0) ? g_qbits : g_kbits)[((size_t)(b * H_ + h)) * S_ + s] = mask;
                }
            } else if (MODE == 0) {
                const int h = head_base + warp_n;
                float* dst = g_vhead + (((size_t)(b * H_ + h)) * S_ + s) * HD;
#pragma unroll
                for (int fn = 0; fn < 8; fn++) {
                    float c0 = acc[fm][fn][half * 2 + 0] + sbias[warp_n * 64 + fn * 8 + gc * 2];
                    float c1 = acc[fm][fn][half * 2 + 1] + sbias[warp_n * 64 + fn * 8 + gc * 2 + 1];
                    float2 f; f.x = (c0 > 0.5f) ? 1.0f : 0.0f; f.y = (c1 > 0.5f) ? 1.0f : 0.0f;
                    *(float2*)(dst + fn * 8 + gc * 2) = f;
                }
            } else {
                float* dst = out + (size_t)row * DM + n0g + warp_n * 64;
#pragma unroll
                for (int fn = 0; fn < 8; fn++) {
                    float c0 = acc[fm][fn][half * 2 + 0] + sbias[warp_n * 64 + fn * 8 + gc * 2];
                    float c1 = acc[fm][fn][half * 2 + 1] + sbias[warp_n * 64 + fn * 8 + gc * 2 + 1];
                    float2 f; f.x = (c0 > 0.5f) ? 1.0f : 0.0f; f.y = (c1 > 0.5f) ? 1.0f : 0.0f;
                    *(float2*)(dst + fn * 8 + gc * 2) = f;
                }
            }
        }
    }
}

// ---------------- attention: popcount scores + squared-softmax + PV ----------------
// s = cnt/8; w2 = e^{2s} = exp2f(cnt * 0.25*log2e). out_d = sum w2 v / Z2.
// (the reference's +1e-8 eps term is <= 2e-5 relative -> dropped)
__global__ void __launch_bounds__(128) attn_kernel() {
    const int KT = 128;
    __shared__ u64 kb[KT];
    __shared__ __align__(16) float vs[KT * HD];   // 32 KB

    const int q0 = blockIdx.x * 128;
    const int h = blockIdx.y;
    const int b = blockIdx.z;
    const int bh = b * H_ + h;
    const int tid = threadIdx.x;

    const u64 q = g_qbits[(size_t)bh * S_ + q0 + tid];

    u64 acc[32];
#pragma unroll
    for (int j = 0; j < 32; j++) acc[j] = 0ull;
    float Z2 = 0.0f;

    const float C2 = 0.36067376022224085f;   // 0.25 * log2(e)

    for (int kt = 0; kt < S_; kt += KT) {
        kb[tid] = g_kbits[(size_t)bh * S_ + kt + tid];
        const float4* vsrc = (const float4*)(g_vhead + ((size_t)bh * S_ + kt) * HD);
        float4* vdst = (float4*)vs;
#pragma unroll
        for (int t = 0; t < 16; t++)
            vdst[t * 128 + tid] = vsrc[t * 128 + tid];
        __syncthreads();

#pragma unroll 2
        for (int kk = 0; kk < KT; kk++) {
            int cnt = __popcll(q & kb[kk]);
            float w2 = exp2f((float)cnt * C2);
            Z2 += w2;
            u64 wp = pack2(w2, w2);
            const float4* vr4 = (const float4*)(vs + kk * HD);
#pragma unroll
            for (int j = 0; j < 16; j++) {
                float4 v4 = vr4[j];
                ffma2(acc[2 * j],     wp, pack2(v4.x, v4.y));
                ffma2(acc[2 * j + 1], wp, pack2(v4.z, v4.w));
            }
        }
        __syncthreads();
    }

    const float inv = 1.0f / Z2;
    const int m = b * S_ + q0 + tid;
    __nv_bfloat162 ob[32];
#pragma unroll
    for (int j = 0; j < 32; j++) {
        F2U t; t.u = acc[j];
        ob[j] = __floats2bfloat162_rn(t.f.x * inv, t.f.y * inv);
    }
    uint4* dst = (uint4*)(g_attnb + (size_t)m * DM + h * HD);
    const uint4* so = (const uint4*)ob;
#pragma unroll
    for (int t = 0; t < 8; t++) dst[t] = so[t];
}

// ---------------- launch ----------------
extern "C" void kernel_launch(void* const* d_in, const int* in_sizes, int n_in,
                              void* d_out, int out_size) {
    const float* x  = (const float*)d_in[0];
    const float* wq = (const float*)d_in[1];
    const float* bq = (const float*)d_in[2];
    const float* wk = (const float*)d_in[3];
    const float* bk = (const float*)d_in[4];
    const float* wv = (const float*)d_in[5];
    const float* bv = (const float*)d_in[6];
    const float* wo = (const float*)d_in[7];
    const float* bo = (const float*)d_in[8];
    float* out = (float*)d_out;

    // fp32 -> bf16 staging (x + 4 weight matrices)
    convert_kernel<<<(XN + 4 * WN) / 4 / 256, 256>>>(x, wq, wk, wv, wo);

    // fused QKV projection (N = 3072 stacked) -> bit masks / head-major V
    gemm_mma<0><<<dim3(24, 32), 256>>>(bq, bk, bv, nullptr);

    // attention
    attn_kernel<<<dim3(S_ / 128, H_, B_), 128>>>();

    // output projection -> d_out (fp32 {0,1})
    gemm_mma<1><<<dim3(8, 32), 256>>>(bo, nullptr, nullptr, out);
}

// round 6
// speedup vs baseline: 6.1528x; 2.8085x over previous
#include <cuda_runtime.h>
#include <cuda_bf16.h>
#include <cstdint>

#define B_    2
#define S_    2048
#define DM    1024
#define H_    16
#define HD    64
#define MROWS 4096
#define XN    (MROWS * DM)      // 4194304
#define WN    (DM * DM)         // 1048576

typedef unsigned long long u64;
typedef unsigned int u32;

// ---------------- scratch (device globals; no allocation allowed) ----------------
__device__ __align__(16) __nv_bfloat16 g_xb[XN];          // x in bf16 (8 MB)
__device__ __align__(16) __nv_bfloat16 g_wb[3 * WN];      // wq|wk|wv stacked bf16 (6 MB)
__device__ __align__(16) __nv_bfloat16 g_wob[WN];         // wo bf16 (2 MB)
__device__ __align__(16) u64  g_qbits[B_ * H_ * S_];      // packed Q bits
__device__ __align__(16) u64  g_kbits[B_ * H_ * S_];      // packed K bits
__device__ __align__(16) __nv_bfloat16 g_vb[B_ * H_ * S_ * HD]; // V head-major bf16 (8 MB)
__device__ __align__(16) __nv_bfloat16 g_attnb[XN];       // attention out bf16 (8 MB)

// ---------------- helpers ----------------
__device__ __forceinline__ u32 smem_u32(const void* p) {
    u32 a;
    asm("{ .reg .u64 t; cvta.to.shared.u64 t, %1; cvt.u32.u64 %0, t; }" : "=r"(a) : "l"(p));
    return a;
}
__device__ __forceinline__ void ldsm_x4(u32* r, u32 addr) {
    asm volatile("ldmatrix.sync.aligned.m8n8.x4.shared.b16 {%0,%1,%2,%3}, [%4];"
        : "=r"(r[0]), "=r"(r[1]), "=r"(r[2]), "=r"(r[3]) : "r"(addr));
}
__device__ __forceinline__ void ldsm_x4_t(u32* r, u32 addr) {
    asm volatile("ldmatrix.sync.aligned.m8n8.x4.trans.shared.b16 {%0,%1,%2,%3}, [%4];"
        : "=r"(r[0]), "=r"(r[1]), "=r"(r[2]), "=r"(r[3]) : "r"(addr));
}
__device__ __forceinline__ void mma16816(float* c, const u32* a, const u32* b) {
    asm volatile("mma.sync.aligned.m16n8k16.row.col.f32.bf16.bf16.f32 "
        "{%0,%1,%2,%3}, {%4,%5,%6,%7}, {%8,%9}, {%0,%1,%2,%3};"
        : "+f"(c[0]), "+f"(c[1]), "+f"(c[2]), "+f"(c[3])
        : "r"(a[0]), "r"(a[1]), "r"(a[2]), "r"(a[3]), "r"(b[0]), "r"(b[1]));
}
__device__ __forceinline__ float ex2(float x) {
    float y; asm("ex2.approx.ftz.f32 %0, %1;" : "=f"(y) : "f"(x)); return y;
}
__device__ __forceinline__ u32 bf2pack(float a, float b) {
    __nv_bfloat162 t = __floats2bfloat162_rn(a, b);
    return *(u32*)&t;
}
#define SW128(o) ((o) ^ ((((u32)(o)) >> 3) & 0x70))

// ---------------- fp32 -> bf16 conversion of x and all weights ----------------
__global__ void __launch_bounds__(256) convert_kernel(const float* __restrict__ x,
                                                      const float* __restrict__ wq,
                                                      const float* __restrict__ wk,
                                                      const float* __restrict__ wv,
                                                      const float* __restrict__ wo) {
    size_t i = ((size_t)blockIdx.x * blockDim.x + threadIdx.x) * 4;
    const float* src;
    __nv_bfloat16* dst;
    size_t off;
    if (i < XN) { src = x; dst = g_xb; off = i; }
    else {
        size_t j = i - XN;
        int w = (int)(j >> 20);
        off = j & (WN - 1);
        src = (w == 0) ? wq : (w == 1) ? wk : (w == 2) ? wv : wo;
        dst = (w < 3) ? (g_wb + (size_t)w * WN) : g_wob;
    }
    float4 v = *(const float4*)(src + off);
    __nv_bfloat162 lo = __floats2bfloat162_rn(v.x, v.y);
    __nv_bfloat162 hi = __floats2bfloat162_rn(v.z, v.w);
    uint2 pk;
    pk.x = *(u32*)&lo; pk.y = *(u32*)&hi;
    *(uint2*)(dst + off) = pk;
}

// ---------------- HMMA GEMM: C = threshold(A @ W^T + bias) ----------------
// MODE 0: A=g_xb, W=g_wb (3072 N-rows: q|k|v), epilogue -> g_qbits/g_kbits masks, g_vb bf16
// MODE 1: A=g_attnb, W=g_wob, epilogue -> out fp32 {0,1}
// CTA tile M=128 N=128, 8 warps as 4(m) x 2(n): warp tile 32x64. K chunks of 64.
template <int MODE>
__global__ void __launch_bounds__(256) gemm_mma(const float* __restrict__ bb0,
                                               const float* __restrict__ bb1,
                                               const float* __restrict__ bb2,
                                               float* __restrict__ out) {
    __shared__ __align__(16) __nv_bfloat16 As[128 * 64];
    __shared__ __align__(16) __nv_bfloat16 Bs[128 * 64];
    __shared__ float sbias[128];

    const int tid = threadIdx.x, lane = tid & 31, wid = tid >> 5;
    const int warp_m = wid & 3, warp_n = wid >> 2;
    const int m0 = blockIdx.y * 128, n0g = blockIdx.x * 128;
    const int p = (MODE == 0) ? (n0g >> 10) : 0;
    const int hd_off = (MODE == 0) ? (n0g & 1023) : n0g;
    const float* bp = (MODE == 0) ? (p == 0 ? bb0 : (p == 1 ? bb1 : bb2)) : bb0;
    const __nv_bfloat16* A = (MODE == 0) ? g_xb : g_attnb;
    const __nv_bfloat16* W = (MODE == 0) ? g_wb : g_wob;

    if (tid < 128) sbias[tid] = bp[hd_off + tid];

    float acc[2][8][4];
#pragma unroll
    for (int fm = 0; fm < 2; fm++)
#pragma unroll
        for (int fn = 0; fn < 8; fn++)
#pragma unroll
            for (int e = 0; e < 4; e++) acc[fm][fn][e] = 0.0f;

    const u32 sA = smem_u32(As), sB = smem_u32(Bs);
    const int a_row = warp_m * 32 + (lane & 15);
    const u32 a_base0 = sA + (u32)a_row * 128;
    const u32 a_base1 = a_base0 + 16 * 128;
    const u32 a_kx = (u32)((lane >> 4) << 4);
    const u32 a_sw = (u32)(a_row & 7) << 4;
    const int b_rin = lane & 7;
    const int b_nadd = ((lane >> 4) & 1) * 8;
    const u32 b_kx = (u32)(((lane >> 3) & 1) << 4);
    const u32 b_sw = (u32)b_rin << 4;
    u32 b_base[4];
#pragma unroll
    for (int g = 0; g < 4; g++)
        b_base[g] = sB + (u32)(warp_n * 64 + g * 16 + b_nadd + b_rin) * 128;

    for (int c = 0; c < 16; c++) {
        const int k0 = c * 64;
#pragma unroll
        for (int i = 0; i < 4; i++) {
            int e = tid + i * 256;
            int row = e >> 3, seg = e & 7;
            u32 so = SW128((u32)(row * 128 + seg * 16));
            *(uint4*)((char*)As + so) = *(const uint4*)(A + (size_t)(m0 + row) * DM + k0 + seg * 8);
            *(uint4*)((char*)Bs + so) = *(const uint4*)(W + (size_t)(n0g + row) * DM + k0 + seg * 8);
        }
        __syncthreads();
#pragma unroll
        for (int kc = 0; kc < 4; kc++) {
            const u32 kb = (u32)(kc * 32);
            u32 af[2][4];
            ldsm_x4(af[0], a_base0 + ((kb + a_kx) ^ a_sw));
            ldsm_x4(af[1], a_base1 + ((kb + a_kx) ^ a_sw));
            u32 bf[4][4];
#pragma unroll
            for (int g = 0; g < 4; g++)
                ldsm_x4(bf[g], b_base[g] + ((kb + b_kx) ^ b_sw));
#pragma unroll
            for (int fm = 0; fm < 2; fm++)
#pragma unroll
                for (int fn = 0; fn < 8; fn++)
                    mma16816(acc[fm][fn], af[fm], &bf[fn >> 1][(fn & 1) * 2]);
        }
        __syncthreads();
    }

    // epilogue: bias + threshold, fused output formats
    const int gr = lane >> 2, gc = lane & 3;
    const int head_base = hd_off >> 6;

#pragma unroll
    for (int fm = 0; fm < 2; fm++) {
#pragma unroll
        for (int half = 0; half < 2; half++) {
            const int row = m0 + warp_m * 32 + fm * 16 + half * 8 + gr;
            const int b = row >> 11, s = row & 2047;

            if (MODE == 0 && p < 2) {
                u64 mask = 0;
#pragma unroll
                for (int fn = 0; fn < 8; fn++) {
                    float c0 = acc[fm][fn][half * 2 + 0] + sbias[warp_n * 64 + fn * 8 + gc * 2];
                    float c1 = acc[fm][fn][half * 2 + 1] + sbias[warp_n * 64 + fn * 8 + gc * 2 + 1];
                    mask |= (u64)(c0 > 0.5f) << (fn * 8 + gc * 2);
                    mask |= (u64)(c1 > 0.5f) << (fn * 8 + gc * 2 + 1);
                }
                mask |= __shfl_xor_sync(0xFFFFFFFFu, mask, 1);
                mask |= __shfl_xor_sync(0xFFFFFFFFu, mask, 2);
                if (gc == 0) {
                    const int h = head_base + warp_n;
                    ((p == 0) ? g_qbits : g_kbits)[((size_t)(b * H_ + h)) * S_ + s] = mask;
                }
            } else if (MODE == 0) {
                const int h = head_base + warp_n;
                __nv_bfloat16* dst = g_vb + (((size_t)(b * H_ + h)) * S_ + s) * HD;
#pragma unroll
                for (int fn = 0; fn < 8; fn++) {
                    float c0 = acc[fm][fn][half * 2 + 0] + sbias[warp_n * 64 + fn * 8 + gc * 2];
                    float c1 = acc[fm][fn][half * 2 + 1] + sbias[warp_n * 64 + fn * 8 + gc * 2 + 1];
                    *(u32*)(dst + fn * 8 + gc * 2) =
                        bf2pack((c0 > 0.5f) ? 1.0f : 0.0f, (c1 > 0.5f) ? 1.0f : 0.0f);
                }
            } else {
                float* dst = out + (size_t)row * DM + n0g + warp_n * 64;
#pragma unroll
                for (int fn = 0; fn < 8; fn++) {
                    float c0 = acc[fm][fn][half * 2 + 0] + sbias[warp_n * 64 + fn * 8 + gc * 2];
                    float c1 = acc[fm][fn][half * 2 + 1] + sbias[warp_n * 64 + fn * 8 + gc * 2 + 1];
                    float2 f; f.x = (c0 > 0.5f) ? 1.0f : 0.0f; f.y = (c1 > 0.5f) ? 1.0f : 0.0f;
                    *(float2*)(dst + fn * 8 + gc * 2) = f;
                }
            }
        }
    }
}

// ---------------- attention: popcount scores -> P in A-frag regs -> HMMA PV ----------------
// w2 = e^{cnt/4} = 2^(cnt * 0.25*log2e). out_d = sum w2 v / Z2 (eps term <=2e-5 rel, dropped).
// Block: 256 thr / 8 warps; warp = 16 q rows; block = 128 q rows of one (b,h).
__global__ void __launch_bounds__(256) attn_kernel() {
    __shared__ __align__(16) u64 kb[128];
    __shared__ __align__(16) __nv_bfloat16 Vs[128 * HD];   // 16 KB, 128B rows, SW128

    const int tid = threadIdx.x, lane = tid & 31, wid = tid >> 5;
    const int gr = lane >> 2, gc = lane & 3;
    const int h = blockIdx.y, b = blockIdx.z;
    const int bh = b * H_ + h;
    const int q0 = blockIdx.x * 128;

    const u64 qlo = g_qbits[(size_t)bh * S_ + q0 + wid * 16 + gr];
    const u64 qhi = g_qbits[(size_t)bh * S_ + q0 + wid * 16 + gr + 8];

    const u32 sV = smem_u32(Vs);
    const u32 vbase = sV + (u32)(lane & 15) * 128;
    u32 boff[4];
    {
        const u32 hi16 = (u32)((lane >> 4) & 1) << 4;
        const u32 swl = (u32)(lane & 7) << 4;
#pragma unroll
        for (int g = 0; g < 4; g++) boff[g] = ((u32)(g * 32) + hi16) ^ swl;
    }

    float acc[8][4];
#pragma unroll
    for (int j = 0; j < 8; j++)
#pragma unroll
        for (int e = 0; e < 4; e++) acc[j][e] = 0.0f;
    float zlo = 0.0f, zhi = 0.0f;
    const float C2 = 0.36067376022224085f;   // 0.25 * log2(e)

    for (int kt = 0; kt < S_; kt += 128) {
        __syncthreads();
        if (tid < 128) kb[tid] = g_kbits[(size_t)bh * S_ + kt + tid];
        {
            const uint4* src = (const uint4*)(g_vb + ((size_t)bh * S_ + kt) * HD);
#pragma unroll
            for (int i = 0; i < 4; i++) {
                int e = tid + i * 256;            // 1024 uint4 = 128 rows x 8 segs
                int row = e >> 3, seg = e & 7;
                u32 so = ((u32)(seg * 16)) ^ ((u32)(row & 7) << 4);
                *(uint4*)((char*)Vs + row * 128 + so) = src[e];
            }
        }
        __syncthreads();

#pragma unroll
        for (int ck = 0; ck < 8; ck++) {
            ulonglong2 p0 = *(const ulonglong2*)&kb[ck * 16 + 2 * gc];
            ulonglong2 p1 = *(const ulonglong2*)&kb[ck * 16 + 8 + 2 * gc];
            float vl0 = ex2((float)__popcll(qlo & p0.x) * C2);
            float vl1 = ex2((float)__popcll(qlo & p0.y) * C2);
            float vh0 = ex2((float)__popcll(qhi & p0.x) * C2);
            float vh1 = ex2((float)__popcll(qhi & p0.y) * C2);
            float vl2 = ex2((float)__popcll(qlo & p1.x) * C2);
            float vl3 = ex2((float)__popcll(qlo & p1.y) * C2);
            float vh2 = ex2((float)__popcll(qhi & p1.x) * C2);
            float vh3 = ex2((float)__popcll(qhi & p1.y) * C2);
            zlo += (vl0 + vl1) + (vl2 + vl3);
            zhi += (vh0 + vh1) + (vh2 + vh3);
            u32 af[4];
            af[0] = bf2pack(vl0, vl1);   // (row gr,   k 2gc,2gc+1)
            af[1] = bf2pack(vh0, vh1);   // (row gr+8, k 2gc,2gc+1)
            af[2] = bf2pack(vl2, vl3);   // (row gr,   k 8+2gc,+1)
            af[3] = bf2pack(vh2, vh3);   // (row gr+8, k 8+2gc,+1)
#pragma unroll
            for (int g = 0; g < 4; g++) {
                u32 bfr[4];
                ldsm_x4_t(bfr, vbase + (u32)(ck * 2048) + boff[g]);
                mma16816(acc[2 * g],     af, bfr);       // d chunk 2g
                mma16816(acc[2 * g + 1], af, bfr + 2);   // d chunk 2g+1
            }
        }
    }

    zlo += __shfl_xor_sync(0xFFFFFFFFu, zlo, 1);
    zlo += __shfl_xor_sync(0xFFFFFFFFu, zlo, 2);
    zhi += __shfl_xor_sync(0xFFFFFFFFu, zhi, 1);
    zhi += __shfl_xor_sync(0xFFFFFFFFu, zhi, 2);
    const float il = 1.0f / zlo, ih = 1.0f / zhi;

    const int sq = q0 + wid * 16 + gr;
    __nv_bfloat16* dlo = g_attnb + ((size_t)(b * S_ + sq)) * DM + h * HD;
    __nv_bfloat16* dhi = dlo + (size_t)8 * DM;
#pragma unroll
    for (int j = 0; j < 8; j++) {
        *(u32*)(dlo + j * 8 + 2 * gc) = bf2pack(acc[j][0] * il, acc[j][1] * il);
        *(u32*)(dhi + j * 8 + 2 * gc) = bf2pack(acc[j][2] * ih, acc[j][3] * ih);
    }
}

// ---------------- launch ----------------
extern "C" void kernel_launch(void* const* d_in, const int* in_sizes, int n_in,
                              void* d_out, int out_size) {
    const float* x  = (const float*)d_in[0];
    const float* wq = (const float*)d_in[1];
    const float* bq = (const float*)d_in[2];
    const float* wk = (const float*)d_in[3];
    const float* bk = (const float*)d_in[4];
    const float* wv = (const float*)d_in[5];
    const float* bv = (const float*)d_in[6];
    const float* wo = (const float*)d_in[7];
    const float* bo = (const float*)d_in[8];
    float* out = (float*)d_out;

    // fp32 -> bf16 staging (x + 4 weight matrices)
    convert_kernel<<<(XN + 4 * WN) / 4 / 256, 256>>>(x, wq, wk, wv, wo);

    // fused QKV projection (N = 3072 stacked) -> bit masks / head-major bf16 V
    gemm_mma<0><<<dim3(24, 32), 256>>>(bq, bk, bv, nullptr);

    // attention (HMMA PV)
    attn_kernel<<<dim3(S_ / 128, H_, B_), 256>>>();

    // output projection -> d_out (fp32 {0,1})
    gemm_mma<1><<<dim3(8, 32), 256>>>(bo, nullptr, nullptr, out);
}

// round 7
// speedup vs baseline: 6.4866x; 1.0542x over previous
#include <cuda_runtime.h>
#include <cuda_bf16.h>
#include <cstdint>

#define B_    2
#define S_    2048
#define DM    1024
#define H_    16
#define HD    64
#define MROWS 4096
#define XN    (MROWS * DM)      // 4194304
#define WN    (DM * DM)         // 1048576

typedef unsigned long long u64;
typedef unsigned int u32;

// ---------------- scratch (device globals; no allocation allowed) ----------------
__device__ __align__(16) __nv_bfloat16 g_xb[XN];          // x in bf16 (8 MB)
__device__ __align__(16) __nv_bfloat16 g_wb[3 * WN];      // wq|wk|wv stacked bf16 (6 MB)
__device__ __align__(16) __nv_bfloat16 g_wob[WN];         // wo bf16 (2 MB)
__device__ __align__(16) u64  g_qbits[B_ * H_ * S_];      // packed Q bits
__device__ __align__(16) u64  g_kbits[B_ * H_ * S_];      // packed K bits
__device__ __align__(16) __nv_bfloat16 g_vb[B_ * H_ * S_ * HD]; // V head-major bf16 (8 MB)
__device__ __align__(16) __nv_bfloat16 g_attnb[XN];       // attention out bf16 (8 MB)

// ---------------- helpers ----------------
__device__ __forceinline__ u32 smem_u32(const void* p) {
    u32 a;
    asm("{ .reg .u64 t; cvta.to.shared.u64 t, %1; cvt.u32.u64 %0, t; }" : "=r"(a) : "l"(p));
    return a;
}
__device__ __forceinline__ void cp16(u32 saddr, const void* gaddr) {
    asm volatile("cp.async.cg.shared.global [%0], [%1], 16;" :: "r"(saddr), "l"(gaddr));
}
__device__ __forceinline__ void cp_commit() { asm volatile("cp.async.commit_group;" ::: "memory"); }
template <int N> __device__ __forceinline__ void cp_wait() {
    asm volatile("cp.async.wait_group %0;" :: "n"(N) : "memory");
}
__device__ __forceinline__ void ldsm_x4(u32* r, u32 addr) {
    asm volatile("ldmatrix.sync.aligned.m8n8.x4.shared.b16 {%0,%1,%2,%3}, [%4];"
        : "=r"(r[0]), "=r"(r[1]), "=r"(r[2]), "=r"(r[3]) : "r"(addr));
}
__device__ __forceinline__ void ldsm_x4_t(u32* r, u32 addr) {
    asm volatile("ldmatrix.sync.aligned.m8n8.x4.trans.shared.b16 {%0,%1,%2,%3}, [%4];"
        : "=r"(r[0]), "=r"(r[1]), "=r"(r[2]), "=r"(r[3]) : "r"(addr));
}
__device__ __forceinline__ void mma16816(float* c, const u32* a, const u32* b) {
    asm volatile("mma.sync.aligned.m16n8k16.row.col.f32.bf16.bf16.f32 "
        "{%0,%1,%2,%3}, {%4,%5,%6,%7}, {%8,%9}, {%0,%1,%2,%3};"
        : "+f"(c[0]), "+f"(c[1]), "+f"(c[2]), "+f"(c[3])
        : "r"(a[0]), "r"(a[1]), "r"(a[2]), "r"(a[3]), "r"(b[0]), "r"(b[1]));
}
__device__ __forceinline__ float ex2(float x) {
    float y; asm("ex2.approx.ftz.f32 %0, %1;" : "=f"(y) : "f"(x)); return y;
}
__device__ __forceinline__ u32 bf2pack(float a, float b) {
    __nv_bfloat162 t = __floats2bfloat162_rn(a, b);
    return *(u32*)&t;
}
#define SW128(o) ((o) ^ ((((u32)(o)) >> 3) & 0x70))

// ---------------- fp32 -> bf16 conversion of x and all weights ----------------
__global__ void __launch_bounds__(256) convert_kernel(const float* __restrict__ x,
                                                      const float* __restrict__ wq,
                                                      const float* __restrict__ wk,
                                                      const float* __restrict__ wv,
                                                      const float* __restrict__ wo) {
    size_t i = ((size_t)blockIdx.x * blockDim.x + threadIdx.x) * 4;
    const float* src;
    __nv_bfloat16* dst;
    size_t off;
    if (i < XN) { src = x; dst = g_xb; off = i; }
    else {
        size_t j = i - XN;
        int w = (int)(j >> 20);
        off = j & (WN - 1);
        src = (w == 0) ? wq : (w == 1) ? wk : (w == 2) ? wv : wo;
        dst = (w < 3) ? (g_wb + (size_t)w * WN) : g_wob;
    }
    float4 v = *(const float4*)(src + off);
    __nv_bfloat162 lo = __floats2bfloat162_rn(v.x, v.y);
    __nv_bfloat162 hi = __floats2bfloat162_rn(v.z, v.w);
    uint2 pk;
    pk.x = *(u32*)&lo; pk.y = *(u32*)&hi;
    *(uint2*)(dst + off) = pk;
}

// ---------------- HMMA GEMM with cp.async double buffering ----------------
// MODE 0: A=g_xb, W=g_wb (3072 N-rows: q|k|v), epilogue -> g_qbits/g_kbits masks, g_vb bf16
// MODE 1: A=g_attnb, W=g_wob, epilogue -> out fp32 {0,1}
// CTA tile M=128 N=128, 8 warps as 4(m) x 2(n): warp tile 32x64. K chunks of 64, 2 stages.
template <int MODE>
__global__ void __launch_bounds__(256) gemm_mma(const float* __restrict__ bb0,
                                               const float* __restrict__ bb1,
                                               const float* __restrict__ bb2,
                                               float* __restrict__ out) {
    __shared__ __align__(16) __nv_bfloat16 As[2][128 * 64];   // 2 x 16 KB
    __shared__ __align__(16) __nv_bfloat16 Bs[2][128 * 64];   // 2 x 16 KB
    __shared__ float sbias[128];

    const int tid = threadIdx.x, lane = tid & 31, wid = tid >> 5;
    const int warp_m = wid & 3, warp_n = wid >> 2;
    const int m0 = blockIdx.y * 128, n0g = blockIdx.x * 128;
    const int p = (MODE == 0) ? (n0g >> 10) : 0;
    const int hd_off = (MODE == 0) ? (n0g & 1023) : n0g;
    const float* bp = (MODE == 0) ? (p == 0 ? bb0 : (p == 1 ? bb1 : bb2)) : bb0;
    const __nv_bfloat16* A = (MODE == 0) ? g_xb : g_attnb;
    const __nv_bfloat16* W = (MODE == 0) ? g_wb : g_wob;

    if (tid < 128) sbias[tid] = bp[hd_off + tid];

    float acc[2][8][4];
#pragma unroll
    for (int fm = 0; fm < 2; fm++)
#pragma unroll
        for (int fn = 0; fn < 8; fn++)
#pragma unroll
            for (int e = 0; e < 4; e++) acc[fm][fn][e] = 0.0f;

    const u32 sA = smem_u32(As), sB = smem_u32(Bs);
    // per-thread cooperative-load geometry: 4 x (row, seg) pairs, swizzled
    const int ld_row = tid >> 3, ld_seg = tid & 7;       // rows tid/8 + {0,32,64,96}
    const u32 ld_so = SW128((u32)(ld_row * 128 + ld_seg * 16));

    // ldmatrix per-thread bases
    const int a_row = warp_m * 32 + (lane & 15);
    const u32 a_off0 = (u32)a_row * 128;
    const u32 a_kx = (u32)((lane >> 4) << 4);
    const u32 a_sw = (u32)(a_row & 7) << 4;
    const int b_rin = lane & 7;
    const int b_nadd = ((lane >> 4) & 1) * 8;
    const u32 b_kx = (u32)(((lane >> 3) & 1) << 4);
    const u32 b_sw = (u32)b_rin << 4;
    u32 b_off[4];
#pragma unroll
    for (int g = 0; g < 4; g++)
        b_off[4 - 1 - g] = (u32)(warp_n * 64 + (3 - g) * 16 + b_nadd + b_rin) * 128;

    // stage-load lambda (issues 8 cp.async + commit)
    auto load_stage = [&](int c, int st) {
        const int k0 = c * 64;
        const u32 aB = sA + (u32)st * 16384 + ld_so;
        const u32 bB = sB + (u32)st * 16384 + ld_so;
#pragma unroll
        for (int i = 0; i < 4; i++) {
            int row = ld_row + i * 32;
            cp16(aB + (u32)(i * 32 * 128), A + (size_t)(m0 + row) * DM + k0 + ld_seg * 8);
            cp16(bB + (u32)(i * 32 * 128), W + (size_t)(n0g + row) * DM + k0 + ld_seg * 8);
        }
        cp_commit();
    };

    load_stage(0, 0);

    for (int c = 0; c < 16; c++) {
        const int st = c & 1;
        if (c + 1 < 16) { load_stage(c + 1, st ^ 1); cp_wait<1>(); }
        else cp_wait<0>();
        __syncthreads();

        const u32 soff = (u32)st * 16384;
        const u32 aBase = sA + soff + a_off0;
        const u32 bBase = sB + soff;
#pragma unroll
        for (int kc = 0; kc < 4; kc++) {
            const u32 kb = (u32)(kc * 32);
            u32 af[2][4];
            ldsm_x4(af[0], aBase + ((kb + a_kx) ^ a_sw));
            ldsm_x4(af[1], aBase + 16 * 128 + ((kb + a_kx) ^ a_sw));
            u32 bf[4][4];
#pragma unroll
            for (int g = 0; g < 4; g++)
                ldsm_x4(bf[g], bBase + b_off[g] + ((kb + b_kx) ^ b_sw));
#pragma unroll
            for (int fm = 0; fm < 2; fm++)
#pragma unroll
                for (int fn = 0; fn < 8; fn++)
                    mma16816(acc[fm][fn], af[fm], &bf[fn >> 1][(fn & 1) * 2]);
        }
        __syncthreads();
    }

    // epilogue: bias + threshold, fused output formats
    const int gr = lane >> 2, gc = lane & 3;
    const int head_base = hd_off >> 6;

#pragma unroll
    for (int fm = 0; fm < 2; fm++) {
#pragma unroll
        for (int half = 0; half < 2; half++) {
            const int row = m0 + warp_m * 32 + fm * 16 + half * 8 + gr;
            const int b = row >> 11, s = row & 2047;

            if (MODE == 0 && p < 2) {
                u64 mask = 0;
#pragma unroll
                for (int fn = 0; fn < 8; fn++) {
                    float c0 = acc[fm][fn][half * 2 + 0] + sbias[warp_n * 64 + fn * 8 + gc * 2];
                    float c1 = acc[fm][fn][half * 2 + 1] + sbias[warp_n * 64 + fn * 8 + gc * 2 + 1];
                    mask |= (u64)(c0 > 0.5f) << (fn * 8 + gc * 2);
                    mask |= (u64)(c1 > 0.5f) << (fn * 8 + gc * 2 + 1);
                }
                mask |= __shfl_xor_sync(0xFFFFFFFFu, mask, 1);
                mask |= __shfl_xor_sync(0xFFFFFFFFu, mask, 2);
                if (gc == 0) {
                    const int h = head_base + warp_n;
                    ((p == 0) ? g_qbits : g_kbits)[((size_t)(b * H_ + h)) * S_ + s] = mask;
                }
            } else if (MODE == 0) {
                const int h = head_base + warp_n;
                __nv_bfloat16* dst = g_vb + (((size_t)(b * H_ + h)) * S_ + s) * HD;
#pragma unroll
                for (int fn = 0; fn < 8; fn++) {
                    float c0 = acc[fm][fn][half * 2 + 0] + sbias[warp_n * 64 + fn * 8 + gc * 2];
                    float c1 = acc[fm][fn][half * 2 + 1] + sbias[warp_n * 64 + fn * 8 + gc * 2 + 1];
                    *(u32*)(dst + fn * 8 + gc * 2) =
                        bf2pack((c0 > 0.5f) ? 1.0f : 0.0f, (c1 > 0.5f) ? 1.0f : 0.0f);
                }
            } else {
                float* dst = out + (size_t)row * DM + n0g + warp_n * 64;
#pragma unroll
                for (int fn = 0; fn < 8; fn++) {
                    float c0 = acc[fm][fn][half * 2 + 0] + sbias[warp_n * 64 + fn * 8 + gc * 2];
                    float c1 = acc[fm][fn][half * 2 + 1] + sbias[warp_n * 64 + fn * 8 + gc * 2 + 1];
                    float2 f; f.x = (c0 > 0.5f) ? 1.0f : 0.0f; f.y = (c1 > 0.5f) ? 1.0f : 0.0f;
                    *(float2*)(dst + fn * 8 + gc * 2) = f;
                }
            }
        }
    }
}

// ---------------- attention: popcount -> P in A-frag regs -> HMMA PV, double-buffered ----------------
// w2 = e^{cnt/4} = 2^(cnt * 0.25*log2e). out_d = sum w2 v / Z2 (eps term <=2e-5 rel, dropped).
__global__ void __launch_bounds__(256) attn_kernel() {
    __shared__ __align__(16) u64 kb[2][128];                       // 2 x 1 KB
    __shared__ __align__(16) __nv_bfloat16 Vs[2][128 * HD];        // 2 x 16 KB

    const int tid = threadIdx.x, lane = tid & 31, wid = tid >> 5;
    const int gr = lane >> 2, gc = lane & 3;
    const int h = blockIdx.y, b = blockIdx.z;
    const int bh = b * H_ + h;
    const int q0 = blockIdx.x * 128;

    const u64 qlo = g_qbits[(size_t)bh * S_ + q0 + wid * 16 + gr];
    const u64 qhi = g_qbits[(size_t)bh * S_ + q0 + wid * 16 + gr + 8];

    const u32 sV = smem_u32(Vs), sK = smem_u32(kb);
    const u32 vbase_off = (u32)(lane & 15) * 128;
    u32 boff[4];
    {
        const u32 hi16 = (u32)((lane >> 4) & 1) << 4;
        const u32 swl = (u32)(lane & 7) << 4;
#pragma unroll
        for (int g = 0; g < 4; g++) boff[g] = ((u32)(g * 32) + hi16) ^ swl;
    }
    const int vld_row = tid >> 1, vld_seg = (tid & 1) * 4;    // 128 rows x 2 halves of 64B

    auto load_stage = [&](int kt, int st) {
        if (tid < 64)
            cp16(sK + (u32)st * 1024 + (u32)tid * 16, &g_kbits[(size_t)bh * S_ + kt + tid * 2]);
        const __nv_bfloat16* src = g_vb + ((size_t)bh * S_ + kt) * HD;
        const u32 vB = sV + (u32)st * 16384;
#pragma unroll
        for (int i = 0; i < 4; i++) {
            int seg = vld_seg + i;
            u32 so = ((u32)(seg * 16)) ^ ((u32)(vld_row & 7) << 4);
            cp16(vB + (u32)vld_row * 128 + so, src + vld_row * HD + seg * 8);
        }
        cp_commit();
    };

    float acc[8][4];
#pragma unroll
    for (int j = 0; j < 8; j++)
#pragma unroll
        for (int e = 0; e < 4; e++) acc[j][e] = 0.0f;
    float zlo = 0.0f, zhi = 0.0f;
    const float C2 = 0.36067376022224085f;   // 0.25 * log2(e)

    load_stage(0, 0);

    for (int kt = 0; kt < S_; kt += 128) {
        const int st = (kt >> 7) & 1;
        if (kt + 128 < S_) { load_stage(kt + 128, st ^ 1); cp_wait<1>(); }
        else cp_wait<0>();
        __syncthreads();

        const u64* kbs = kb[st];
        const u32 vbase = sV + (u32)st * 16384 + vbase_off;
#pragma unroll
        for (int ck = 0; ck < 8; ck++) {
            ulonglong2 p0 = *(const ulonglong2*)&kbs[ck * 16 + 2 * gc];
            ulonglong2 p1 = *(const ulonglong2*)&kbs[ck * 16 + 8 + 2 * gc];
            float vl0 = ex2((float)__popcll(qlo & p0.x) * C2);
            float vl1 = ex2((float)__popcll(qlo & p0.y) * C2);
            float vh0 = ex2((float)__popcll(qhi & p0.x) * C2);
            float vh1 = ex2((float)__popcll(qhi & p0.y) * C2);
            float vl2 = ex2((float)__popcll(qlo & p1.x) * C2);
            float vl3 = ex2((float)__popcll(qlo & p1.y) * C2);
            float vh2 = ex2((float)__popcll(qhi & p1.x) * C2);
            float vh3 = ex2((float)__popcll(qhi & p1.y) * C2);
            zlo += (vl0 + vl1) + (vl2 + vl3);
            zhi += (vh0 + vh1) + (vh2 + vh3);
            u32 af[4];
            af[0] = bf2pack(vl0, vl1);
            af[1] = bf2pack(vh0, vh1);
            af[2] = bf2pack(vl2, vl3);
            af[3] = bf2pack(vh2, vh3);
#pragma unroll
            for (int g = 0; g < 4; g++) {
                u32 bfr[4];
                ldsm_x4_t(bfr, vbase + (u32)(ck * 2048) + boff[g]);
                mma16816(acc[2 * g],     af, bfr);
                mma16816(acc[2 * g + 1], af, bfr + 2);
            }
        }
        __syncthreads();
    }

    zlo += __shfl_xor_sync(0xFFFFFFFFu, zlo, 1);
    zlo += __shfl_xor_sync(0xFFFFFFFFu, zlo, 2);
    zhi += __shfl_xor_sync(0xFFFFFFFFu, zhi, 1);
    zhi += __shfl_xor_sync(0xFFFFFFFFu, zhi, 2);
    const float il = 1.0f / zlo, ih = 1.0f / zhi;

    const int sq = q0 + wid * 16 + gr;
    __nv_bfloat16* dlo = g_attnb + ((size_t)(b * S_ + sq)) * DM + h * HD;
    __nv_bfloat16* dhi = dlo + (size_t)8 * DM;
#pragma unroll
    for (int j = 0; j < 8; j++) {
        *(u32*)(dlo + j * 8 + 2 * gc) = bf2pack(acc[j][0] * il, acc[j][1] * il);
        *(u32*)(dhi + j * 8 + 2 * gc) = bf2pack(acc[j][2] * ih, acc[j][3] * ih);
    }
}

// ---------------- launch ----------------
extern "C" void kernel_launch(void* const* d_in, const int* in_sizes, int n_in,
                              void* d_out, int out_size) {
    const float* x  = (const float*)d_in[0];
    const float* wq = (const float*)d_in[1];
    const float* bq = (const float*)d_in[2];
    const float* wk = (const float*)d_in[3];
    const float* bk = (const float*)d_in[4];
    const float* wv = (const float*)d_in[5];
    const float* bv = (const float*)d_in[6];
    const float* wo = (const float*)d_in[7];
    const float* bo = (const float*)d_in[8];
    float* out = (float*)d_out;

    // fp32 -> bf16 staging (x + 4 weight matrices)
    convert_kernel<<<(XN + 4 * WN) / 4 / 256, 256>>>(x, wq, wk, wv, wo);

    // fused QKV projection (N = 3072 stacked) -> bit masks / head-major bf16 V
    gemm_mma<0><<<dim3(24, 32), 256>>>(bq, bk, bv, nullptr);

    // attention (HMMA PV, double-buffered)
    attn_kernel<<<dim3(S_ / 128, H_, B_), 256>>>();

    // output projection -> d_out (fp32 {0,1})
    gemm_mma<1><<<dim3(8, 32), 256>>>(bo, nullptr, nullptr, out);
}

// round 8
// speedup vs baseline: 6.7094x; 1.0344x over previous
#include <cuda_runtime.h>
#include <cuda_bf16.h>
#include <cstdint>

#define B_    2
#define S_    2048
#define DM    1024
#define H_    16
#define HD    64
#define MROWS 4096
#define XN    (MROWS * DM)      // 4194304
#define WN    (DM * DM)         // 1048576

typedef unsigned long long u64;
typedef unsigned int u32;

// ---------------- scratch (device globals; no allocation allowed) ----------------
__device__ __align__(16) __nv_bfloat16 g_xb[XN];          // x in bf16 (8 MB)
__device__ __align__(16) __nv_bfloat16 g_wb[3 * WN];      // wq|wk|wv stacked bf16 (6 MB)
__device__ __align__(16) __nv_bfloat16 g_wob[WN];         // wo bf16 (2 MB)
__device__ __align__(16) u64  g_qbits[B_ * H_ * S_];      // packed Q bits
__device__ __align__(16) u64  g_kbits[B_ * H_ * S_];      // packed K bits
__device__ __align__(16) __nv_bfloat16 g_vb[B_ * H_ * S_ * HD]; // V head-major bf16 (8 MB)
__device__ __align__(16) __nv_bfloat16 g_attnb[XN];       // attention out bf16 (8 MB)

// ---------------- helpers ----------------
__device__ __forceinline__ u32 smem_u32(const void* p) {
    u32 a;
    asm("{ .reg .u64 t; cvta.to.shared.u64 t, %1; cvt.u32.u64 %0, t; }" : "=r"(a) : "l"(p));
    return a;
}
__device__ __forceinline__ void cp16(u32 saddr, const void* gaddr) {
    asm volatile("cp.async.cg.shared.global [%0], [%1], 16;" :: "r"(saddr), "l"(gaddr));
}
__device__ __forceinline__ void cp_commit() { asm volatile("cp.async.commit_group;" ::: "memory"); }
template <int N> __device__ __forceinline__ void cp_wait() {
    asm volatile("cp.async.wait_group %0;" :: "n"(N) : "memory");
}
__device__ __forceinline__ void ldsm_x4(u32* r, u32 addr) {
    asm volatile("ldmatrix.sync.aligned.m8n8.x4.shared.b16 {%0,%1,%2,%3}, [%4];"
        : "=r"(r[0]), "=r"(r[1]), "=r"(r[2]), "=r"(r[3]) : "r"(addr));
}
__device__ __forceinline__ void ldsm_x4_t(u32* r, u32 addr) {
    asm volatile("ldmatrix.sync.aligned.m8n8.x4.trans.shared.b16 {%0,%1,%2,%3}, [%4];"
        : "=r"(r[0]), "=r"(r[1]), "=r"(r[2]), "=r"(r[3]) : "r"(addr));
}
__device__ __forceinline__ void mma16816(float* c, const u32* a, const u32* b) {
    asm volatile("mma.sync.aligned.m16n8k16.row.col.f32.bf16.bf16.f32 "
        "{%0,%1,%2,%3}, {%4,%5,%6,%7}, {%8,%9}, {%0,%1,%2,%3};"
        : "+f"(c[0]), "+f"(c[1]), "+f"(c[2]), "+f"(c[3])
        : "r"(a[0]), "r"(a[1]), "r"(a[2]), "r"(a[3]), "r"(b[0]), "r"(b[1]));
}
__device__ __forceinline__ float ex2(float x) {
    float y; asm("ex2.approx.ftz.f32 %0, %1;" : "=f"(y) : "f"(x)); return y;
}
__device__ __forceinline__ u32 bf2pack(float a, float b) {
    __nv_bfloat162 t = __floats2bfloat162_rn(a, b);
    return *(u32*)&t;
}
#define SW128(o) ((o) ^ ((((u32)(o)) >> 3) & 0x70))

// ---------------- fp32 -> bf16 conversion of x and all weights ----------------
__global__ void __launch_bounds__(256) convert_kernel(const float* __restrict__ x,
                                                      const float* __restrict__ wq,
                                                      const float* __restrict__ wk,
                                                      const float* __restrict__ wv,
                                                      const float* __restrict__ wo) {
    size_t i = ((size_t)blockIdx.x * blockDim.x + threadIdx.x) * 4;
    const float* src;
    __nv_bfloat16* dst;
    size_t off;
    if (i < XN) { src = x; dst = g_xb; off = i; }
    else {
        size_t j = i - XN;
        int w = (int)(j >> 20);
        off = j & (WN - 1);
        src = (w == 0) ? wq : (w == 1) ? wk : (w == 2) ? wv : wo;
        dst = (w < 3) ? (g_wb + (size_t)w * WN) : g_wob;
    }
    float4 v = *(const float4*)(src + off);
    __nv_bfloat162 lo = __floats2bfloat162_rn(v.x, v.y);
    __nv_bfloat162 hi = __floats2bfloat162_rn(v.z, v.w);
    uint2 pk;
    pk.x = *(u32*)&lo; pk.y = *(u32*)&hi;
    *(uint2*)(dst + off) = pk;
}

// ---------------- HMMA GEMM: 3-stage cp.async pipeline ----------------
// MODE 0: A=g_xb, W=g_wb (3072 N-rows: q|k|v), epilogue -> g_qbits/g_kbits masks, g_vb bf16
// MODE 1: A=g_attnb, W=g_wob, epilogue -> out fp32 {0,1}
// CTA tile M=128 N=128, 8 warps as 4(m) x 2(n). K chunks of 64, 3 stages, distance-2 prefetch.
template <int MODE>
__global__ void __launch_bounds__(256) gemm_mma(const float* __restrict__ bb0,
                                               const float* __restrict__ bb1,
                                               const float* __restrict__ bb2,
                                               float* __restrict__ out) {
    __shared__ __align__(16) __nv_bfloat16 As[3][128 * 64];   // 3 x 16 KB
    __shared__ __align__(16) __nv_bfloat16 Bs[3][128 * 64];   // 3 x 16 KB
    __shared__ float sbias[128];

    const int tid = threadIdx.x, lane = tid & 31, wid = tid >> 5;
    const int warp_m = wid & 3, warp_n = wid >> 2;
    const int m0 = blockIdx.y * 128, n0g = blockIdx.x * 128;
    const int p = (MODE == 0) ? (n0g >> 10) : 0;
    const int hd_off = (MODE == 0) ? (n0g & 1023) : n0g;
    const float* bp = (MODE == 0) ? (p == 0 ? bb0 : (p == 1 ? bb1 : bb2)) : bb0;
    const __nv_bfloat16* A = (MODE == 0) ? g_xb : g_attnb;
    const __nv_bfloat16* W = (MODE == 0) ? g_wb : g_wob;

    if (tid < 128) sbias[tid] = bp[hd_off + tid];

    float acc[2][8][4];
#pragma unroll
    for (int fm = 0; fm < 2; fm++)
#pragma unroll
        for (int fn = 0; fn < 8; fn++)
#pragma unroll
            for (int e = 0; e < 4; e++) acc[fm][fn][e] = 0.0f;

    const u32 sA = smem_u32(As), sB = smem_u32(Bs);
    const int ld_row = tid >> 3, ld_seg = tid & 7;
    const u32 ld_so = SW128((u32)(ld_row * 128 + ld_seg * 16));

    const int a_row = warp_m * 32 + (lane & 15);
    const u32 a_off0 = (u32)a_row * 128;
    const u32 a_kx = (u32)((lane >> 4) << 4);
    const u32 a_sw = (u32)(a_row & 7) << 4;
    const int b_rin = lane & 7;
    const int b_nadd = ((lane >> 4) & 1) * 8;
    const u32 b_kx = (u32)(((lane >> 3) & 1) << 4);
    const u32 b_sw = (u32)b_rin << 4;
    u32 b_off[4];
#pragma unroll
    for (int g = 0; g < 4; g++)
        b_off[g] = (u32)(warp_n * 64 + g * 16 + b_nadd + b_rin) * 128;

    auto load_stage = [&](int c, int st) {
        const int k0 = c * 64;
        const u32 aB = sA + (u32)st * 16384 + ld_so;
        const u32 bB = sB + (u32)st * 16384 + ld_so;
#pragma unroll
        for (int i = 0; i < 4; i++) {
            int row = ld_row + i * 32;
            cp16(aB + (u32)(i * 32 * 128), A + (size_t)(m0 + row) * DM + k0 + ld_seg * 8);
            cp16(bB + (u32)(i * 32 * 128), W + (size_t)(n0g + row) * DM + k0 + ld_seg * 8);
        }
        cp_commit();
    };

    load_stage(0, 0);
    load_stage(1, 1);

    int st = 0;
    for (int c = 0; c < 16; c++) {
        if (c < 15) cp_wait<1>(); else cp_wait<0>();
        __syncthreads();

        const u32 soff = (u32)st * 16384;
        const u32 aBase = sA + soff + a_off0;
        const u32 bBase = sB + soff;
#pragma unroll
        for (int kc = 0; kc < 4; kc++) {
            const u32 kb = (u32)(kc * 32);
            u32 af[2][4];
            ldsm_x4(af[0], aBase + ((kb + a_kx) ^ a_sw));
            ldsm_x4(af[1], aBase + 16 * 128 + ((kb + a_kx) ^ a_sw));
            u32 bf[4][4];
#pragma unroll
            for (int g = 0; g < 4; g++)
                ldsm_x4(bf[g], bBase + b_off[g] + ((kb + b_kx) ^ b_sw));
#pragma unroll
            for (int fm = 0; fm < 2; fm++)
#pragma unroll
                for (int fn = 0; fn < 8; fn++)
                    mma16816(acc[fm][fn], af[fm], &bf[fn >> 1][(fn & 1) * 2]);
        }

        if (c + 2 < 16) {
            int st2 = st + 2; if (st2 >= 3) st2 -= 3;
            load_stage(c + 2, st2);
        }
        if (++st == 3) st = 0;
    }

    // epilogue: bias + threshold, fused output formats
    const int gr = lane >> 2, gc = lane & 3;
    const int head_base = hd_off >> 6;

#pragma unroll
    for (int fm = 0; fm < 2; fm++) {
#pragma unroll
        for (int half = 0; half < 2; half++) {
            const int row = m0 + warp_m * 32 + fm * 16 + half * 8 + gr;
            const int b = row >> 11, s = row & 2047;

            if (MODE == 0 && p < 2) {
                u64 mask = 0;
#pragma unroll
                for (int fn = 0; fn < 8; fn++) {
                    float c0 = acc[fm][fn][half * 2 + 0] + sbias[warp_n * 64 + fn * 8 + gc * 2];
                    float c1 = acc[fm][fn][half * 2 + 1] + sbias[warp_n * 64 + fn * 8 + gc * 2 + 1];
                    mask |= (u64)(c0 > 0.5f) << (fn * 8 + gc * 2);
                    mask |= (u64)(c1 > 0.5f) << (fn * 8 + gc * 2 + 1);
                }
                mask |= __shfl_xor_sync(0xFFFFFFFFu, mask, 1);
                mask |= __shfl_xor_sync(0xFFFFFFFFu, mask, 2);
                if (gc == 0) {
                    const int h = head_base + warp_n;
                    ((p == 0) ? g_qbits : g_kbits)[((size_t)(b * H_ + h)) * S_ + s] = mask;
                }
            } else if (MODE == 0) {
                const int h = head_base + warp_n;
                __nv_bfloat16* dst = g_vb + (((size_t)(b * H_ + h)) * S_ + s) * HD;
#pragma unroll
                for (int fn = 0; fn < 8; fn++) {
                    float c0 = acc[fm][fn][half * 2 + 0] + sbias[warp_n * 64 + fn * 8 + gc * 2];
                    float c1 = acc[fm][fn][half * 2 + 1] + sbias[warp_n * 64 + fn * 8 + gc * 2 + 1];
                    *(u32*)(dst + fn * 8 + gc * 2) =
                        bf2pack((c0 > 0.5f) ? 1.0f : 0.0f, (c1 > 0.5f) ? 1.0f : 0.0f);
                }
            } else {
                float* dst = out + (size_t)row * DM + n0g + warp_n * 64;
#pragma unroll
                for (int fn = 0; fn < 8; fn++) {
                    float c0 = acc[fm][fn][half * 2 + 0] + sbias[warp_n * 64 + fn * 8 + gc * 2];
                    float c1 = acc[fm][fn][half * 2 + 1] + sbias[warp_n * 64 + fn * 8 + gc * 2 + 1];
                    float2 f; f.x = (c0 > 0.5f) ? 1.0f : 0.0f; f.y = (c1 > 0.5f) ? 1.0f : 0.0f;
                    *(float2*)(dst + fn * 8 + gc * 2) = f;
                }
            }
        }
    }
}

// ---------------- attention: popcount -> P in A-frag regs -> HMMA PV, 3-stage pipeline ----------------
// w2 = e^{cnt/4} = 2^(cnt * 0.25*log2e). out_d = sum w2 v / Z2 (eps term <=2e-5 rel, dropped).
__global__ void __launch_bounds__(256) attn_kernel() {
    __shared__ __align__(16) u64 kb[3][128];                       // 3 x 1 KB
    __shared__ __align__(16) __nv_bfloat16 Vs[3][128 * HD];        // 3 x 16 KB

    const int tid = threadIdx.x, lane = tid & 31, wid = tid >> 5;
    const int gr = lane >> 2, gc = lane & 3;
    const int h = blockIdx.y, b = blockIdx.z;
    const int bh = b * H_ + h;
    const int q0 = blockIdx.x * 128;

    const u64 qlo = g_qbits[(size_t)bh * S_ + q0 + wid * 16 + gr];
    const u64 qhi = g_qbits[(size_t)bh * S_ + q0 + wid * 16 + gr + 8];

    const u32 sV = smem_u32(Vs), sK = smem_u32(kb);
    const u32 vbase_off = (u32)(lane & 15) * 128;
    u32 boff[4];
    {
        const u32 hi16 = (u32)((lane >> 4) & 1) << 4;
        const u32 swl = (u32)(lane & 7) << 4;
#pragma unroll
        for (int g = 0; g < 4; g++) boff[g] = ((u32)(g * 32) + hi16) ^ swl;
    }
    const int vld_row = tid >> 1, vld_seg = (tid & 1) * 4;

    auto load_stage = [&](int it, int st) {
        const int kt = it * 128;
        if (tid < 64)
            cp16(sK + (u32)st * 1024 + (u32)tid * 16, &g_kbits[(size_t)bh * S_ + kt + tid * 2]);
        const __nv_bfloat16* src = g_vb + ((size_t)bh * S_ + kt) * HD;
        const u32 vB = sV + (u32)st * 16384;
#pragma unroll
        for (int i = 0; i < 4; i++) {
            int seg = vld_seg + i;
            u32 so = ((u32)(seg * 16)) ^ ((u32)(vld_row & 7) << 4);
            cp16(vB + (u32)vld_row * 128 + so, src + vld_row * HD + seg * 8);
        }
        cp_commit();
    };

    float acc[8][4];
#pragma unroll
    for (int j = 0; j < 8; j++)
#pragma unroll
        for (int e = 0; e < 4; e++) acc[j][e] = 0.0f;
    float zlo = 0.0f, zhi = 0.0f;
    const float C2 = 0.36067376022224085f;   // 0.25 * log2(e)

    load_stage(0, 0);
    load_stage(1, 1);

    int st = 0;
    for (int it = 0; it < 16; it++) {
        if (it < 15) cp_wait<1>(); else cp_wait<0>();
        __syncthreads();

        const u64* kbs = kb[st];
        const u32 vbase = sV + (u32)st * 16384 + vbase_off;
#pragma unroll
        for (int ck = 0; ck < 8; ck++) {
            // hoist V fragments: LDSM latency hides under P-generation ALU below
            u32 bfr[4][4];
#pragma unroll
            for (int g = 0; g < 4; g++)
                ldsm_x4_t(bfr[g], vbase + (u32)(ck * 2048) + boff[g]);

            ulonglong2 p0 = *(const ulonglong2*)&kbs[ck * 16 + 2 * gc];
            ulonglong2 p1 = *(const ulonglong2*)&kbs[ck * 16 + 8 + 2 * gc];
            float vl0 = ex2((float)__popcll(qlo & p0.x) * C2);
            float vl1 = ex2((float)__popcll(qlo & p0.y) * C2);
            float vh0 = ex2((float)__popcll(qhi & p0.x) * C2);
            float vh1 = ex2((float)__popcll(qhi & p0.y) * C2);
            float vl2 = ex2((float)__popcll(qlo & p1.x) * C2);
            float vl3 = ex2((float)__popcll(qlo & p1.y) * C2);
            float vh2 = ex2((float)__popcll(qhi & p1.x) * C2);
            float vh3 = ex2((float)__popcll(qhi & p1.y) * C2);
            zlo += (vl0 + vl1) + (vl2 + vl3);
            zhi += (vh0 + vh1) + (vh2 + vh3);
            u32 af[4];
            af[0] = bf2pack(vl0, vl1);
            af[1] = bf2pack(vh0, vh1);
            af[2] = bf2pack(vl2, vl3);
            af[3] = bf2pack(vh2, vh3);
#pragma unroll
            for (int g = 0; g < 4; g++) {
                mma16816(acc[2 * g],     af, bfr[g]);
                mma16816(acc[2 * g + 1], af, bfr[g] + 2);
            }
        }

        if (it + 2 < 16) {
            int st2 = st + 2; if (st2 >= 3) st2 -= 3;
            load_stage(it + 2, st2);
        }
        if (++st == 3) st = 0;
    }

    zlo += __shfl_xor_sync(0xFFFFFFFFu, zlo, 1);
    zlo += __shfl_xor_sync(0xFFFFFFFFu, zlo, 2);
    zhi += __shfl_xor_sync(0xFFFFFFFFu, zhi, 1);
    zhi += __shfl_xor_sync(0xFFFFFFFFu, zhi, 2);
    const float il = 1.0f / zlo, ih = 1.0f / zhi;

    const int sq = q0 + wid * 16 + gr;
    __nv_bfloat16* dlo = g_attnb + ((size_t)(b * S_ + sq)) * DM + h * HD;
    __nv_bfloat16* dhi = dlo + (size_t)8 * DM;
#pragma unroll
    for (int j = 0; j < 8; j++) {
        *(u32*)(dlo + j * 8 + 2 * gc) = bf2pack(acc[j][0] * il, acc[j][1] * il);
        *(u32*)(dhi + j * 8 + 2 * gc) = bf2pack(acc[j][2] * ih, acc[j][3] * ih);
    }
}

// ---------------- launch ----------------
extern "C" void kernel_launch(void* const* d_in, const int* in_sizes, int n_in,
                              void* d_out, int out_size) {
    const float* x  = (const float*)d_in[0];
    const float* wq = (const float*)d_in[1];
    const float* bq = (const float*)d_in[2];
    const float* wk = (const float*)d_in[3];
    const float* bk = (const float*)d_in[4];
    const float* wv = (const float*)d_in[5];
    const float* bv = (const float*)d_in[6];
    const float* wo = (const float*)d_in[7];
    const float* bo = (const float*)d_in[8];
    float* out = (float*)d_out;

    // fp32 -> bf16 staging (x + 4 weight matrices)
    convert_kernel<<<(XN + 4 * WN) / 4 / 256, 256>>>(x, wq, wk, wv, wo);

    // fused QKV projection (N = 3072 stacked) -> bit masks / head-major bf16 V
    gemm_mma<0><<<dim3(24, 32), 256>>>(bq, bk, bv, nullptr);

    // attention (HMMA PV, 3-stage pipeline)
    attn_kernel<<<dim3(S_ / 128, H_, B_), 256>>>();

    // output projection -> d_out (fp32 {0,1})
    gemm_mma<1><<<dim3(8, 32), 256>>>(bo, nullptr, nullptr, out);
}